// round 7
// baseline (speedup 1.0000x reference)
#include <cuda_runtime.h>
#include <math.h>

// ---------------- problem constants (static in reference) ----------------
#define N_SAMPLES 4410000
#define WSZ       441          // wavetable size
#define BB        40           // chunks per block
#define GG        250          // number of blocks (BB*GG == 10000 chunks)
#define KH        4            // recurrence steps per barrier (halo depth)
#define NG        (BB / KH)    // 10 barrier groups
#define R21       21           // radix (441 = 21*21)
#define NTHR      448          // threads per CTA (441 active)
#define NV4       4410         // float4 count of one fb tile (BB*WSZ/4)

#define PI_F      3.14159265358979f
#define TWOPI_F   6.2831853071795864f
#define SR_F      44100.0f

// ---------------- device scratch ----------------------------------------
__device__ float g_what[2 * WSZ];      // DFT of wavetable
__device__ float g_lamB[2 * WSZ];      // lambda^BB per bin
__device__ float g_Ehat[GG * 2 * WSZ]; // per-block forced end-state spectra
__device__ float g_Shat[GG * 2 * WSZ]; // per-block entering-state spectra
__device__ float g_scal[8];            // 0:c 1:fa 2:sA 3:inv_a 5:inv_r 6:T

// ---------------- parallel biquad via affine scan (441 active lanes) -----
__device__ void biquad_par(const float* __restrict__ x, float* __restrict__ y,
                           float f, float q, int tid, bool act,
                           float* sb1, float* sb2, float (*sMp)[4]) {
    float w0   = (TWOPI_F * f) / SR_F;
    float cosw = cosf(w0);
    float alpha = sinf(w0) / (2.0f * q);
    float b0 = (1.0f - cosw) / 2.0f;
    float b1c = 1.0f - cosw;
    float b2c = (1.0f - cosw) / 2.0f;
    float a0 = 1.0f + alpha;
    float a1 = -2.0f * cosw;
    float a2 = 1.0f - alpha;
    b0 /= a0; b1c /= a0; b2c /= a0; a1 /= a0; a2 /= a0;
    float d1 = b1c - a1 * b0;
    float d2 = b2c - a2 * b0;

    if (tid == 0) {
        float A0 = -a1, A1 = 1.0f, A2 = -a2, A3 = 0.0f;
        #pragma unroll
        for (int dd = 0; dd < 9; dd++) {
            sMp[dd][0] = A0; sMp[dd][1] = A1; sMp[dd][2] = A2; sMp[dd][3] = A3;
            float n0 = A0 * A0 + A1 * A2;
            float n1 = A0 * A1 + A1 * A3;
            float n2 = A2 * A0 + A3 * A2;
            float n3 = A2 * A1 + A3 * A3;
            A0 = n0; A1 = n1; A2 = n2; A3 = n3;
        }
    }
    float xv = 0.0f;
    if (act) {
        xv = x[tid];
        sb1[tid] = xv * d1;
        sb2[tid] = xv * d2;
    }
    __syncthreads();
    #pragma unroll
    for (int dd = 0; dd < 9; dd++) {
        int off = 1 << dd;
        float p1 = 0.0f, p2 = 0.0f;
        bool upd = act && (tid >= off);
        if (upd) { p1 = sb1[tid - off]; p2 = sb2[tid - off]; }
        float m0 = sMp[dd][0], m1 = sMp[dd][1], m2 = sMp[dd][2], m3 = sMp[dd][3];
        __syncthreads();
        if (upd) {
            sb1[tid] = fmaf(m0, p1, fmaf(m1, p2, sb1[tid]));
            sb2[tid] = fmaf(m2, p1, fmaf(m3, p2, sb2[tid]));
        }
        __syncthreads();
    }
    if (act) {
        float s1 = (tid == 0) ? 0.0f : sb1[tid - 1];
        y[tid] = fmaf(b0, xv, s1);
    }
    __syncthreads();
}

// ---------------- radix-21 forward DFT (smem -> per-thread register bin) --
__device__ __forceinline__ void dft441_fwd_reg(const float* __restrict__ sx,
                                               float* __restrict__ t_re,
                                               float* __restrict__ t_im,
                                               int tid, bool act,
                                               float* oRe, float* oIm) {
    if (act) {   // stage 1: tid = mmod*21 + i0
        int mmod = tid / R21, i0 = tid % R21;
        float ang = -TWOPI_F * (float)mmod / 21.0f;
        float c0, s0; sincosf(ang, &s0, &c0);
        float wc = 1.0f, ws = 0.0f, re = 0.0f, im = 0.0f;
        #pragma unroll
        for (int i1 = 0; i1 < R21; i1++) {
            float v = sx[i0 + R21 * i1];
            re = fmaf(v, wc, re);
            im = fmaf(v, ws, im);
            float nw = wc * c0 - ws * s0;
            ws = fmaf(wc, s0, ws * c0);
            wc = nw;
        }
        t_re[tid] = re; t_im[tid] = im;
    }
    __syncthreads();
    if (act) {   // stage 2: tid = m
        int m = tid, mm = m % R21;
        float ang = -TWOPI_F * (float)m / 441.0f;
        float c0, s0; sincosf(ang, &s0, &c0);
        float wc = 1.0f, ws = 0.0f, re = 0.0f, im = 0.0f;
        const float* gr = t_re + mm * R21;
        const float* gi = t_im + mm * R21;
        #pragma unroll
        for (int i0 = 0; i0 < R21; i0++) {
            float a = gr[i0], b = gi[i0];
            re = fmaf(a, wc, fmaf(-b, ws, re));
            im = fmaf(a, ws, fmaf( b, wc, im));
            float nw = wc * c0 - ws * s0;
            ws = fmaf(wc, s0, ws * c0);
            wc = nw;
        }
        *oRe = re; *oIm = im;
    }
    __syncthreads();   // callers reuse the temps after this
}

// ---------------- K_A: MLP (all CTAs) + full setup (CTA0) + pass A --------
__global__ __launch_bounds__(NTHR, 2)
void k_passA(const float* __restrict__ fb,   const float* __restrict__ h,
             const float* __restrict__ noise, const float* __restrict__ W1,
             const float* __restrict__ b1,   const float* __restrict__ W2,
             const float* __restrict__ b2,   const float* __restrict__ lp,
             const float* __restrict__ env,  float* __restrict__ out) {
    extern __shared__ float smx[];
    float* sfb = smx;                  // BB*WSZ = 17640 floats
    float* aux = smx + BB * WSZ;       // 6*WSZ = 2646 floats

    int tid = threadIdx.x;
    int g   = blockIdx.x;
    bool act = tid < WSZ;

    // ---- stage fb tile as float4 (4410 vectors) ----
    {
        const float4* f4 = (const float4*)(fb + (size_t)g * BB * WSZ);
        float4* s4 = (float4*)sfb;
        #pragma unroll
        for (int k = 0; k < 9; k++) s4[tid + NTHR * k] = f4[tid + NTHR * k];
        if (tid < NV4 - 9 * NTHR) s4[tid + 9 * NTHR] = f4[tid + 9 * NTHR];
    }

    float* sx   = aux;                    // WSZ
    float* sy   = aux + WSZ;              // WSZ
    float* sb1  = aux + 2 * WSZ;          // WSZ
    float* sb2  = aux + 3 * WSZ;          // WSZ
    float* shid = aux + 4 * WSZ;          // 128
    float* slat = aux + 4 * WSZ + 128;    // 5
    float (*sMp)[4] = (float(*)[4])(aux + 4 * WSZ + 160); // 36

    // ---- tiny MLP (every CTA): hidden layer then 160-lane shfl-reduce ----
    if (tid < 128) {
        float acc = b1[tid];
        #pragma unroll
        for (int i = 0; i < 9; i++) acc += h[i] * W1[i * 128 + tid];
        shid[tid] = fmaxf(acc, 0.0f);
    }
    __syncthreads();
    if (tid < 160) {
        int o = tid >> 5, j0 = tid & 31;
        float acc = 0.0f;
        #pragma unroll
        for (int r = 0; r < 4; r++) {
            int j = j0 + 32 * r;
            acc = fmaf(shid[j], W2[j * 5 + o], acc);
        }
        #pragma unroll
        for (int off = 16; off > 0; off >>= 1)
            acc += __shfl_down_sync(0xffffffffu, acc, off);
        if (j0 == 0) slat[o] = fmaxf(acc + b2[o], 0.0f);
    }
    __syncthreads();

    float decay = fminf(fmaxf(slat[0] / 10.0f + 0.9f, 0.9f), 0.999f);
    float fa    = slat[3];
    float c     = decay * 0.5f;

    // ---- full setup: CTA 0 only (biquads, What, lamB, scalars) ----
    if (g == 0) {
        float lpf = fminf(fmaxf(slat[1] * SR_F / 4.0f, 100.0f), SR_F / 2.0f - 1.0f);
        float lpq = fminf(fmaxf(slat[2], 0.1f), 0.999f);
        if (act) sx[tid] = noise[tid];
        __syncthreads();
        biquad_par(sx, sy, lpf, lpq, tid, act, sb1, sb2, sMp);
        biquad_par(sy, sx, lp[0], 0.707f, tid, act, sb1, sb2, sMp);
        // sx = wavetable wt
        if (tid == 0) {
            g_scal[0] = c;
            g_scal[1] = fa;
            g_scal[2] = env[1] * slat[4];               // s * gain
            g_scal[3] = 1.0f / (fabsf(env[0]) + 1e-3f); // 1/attack
            g_scal[5] = 1.0f / (fabsf(env[2]) + 1e-3f); // 1/release
            g_scal[6] = (float)(N_SAMPLES - 1) / SR_F;  // T == t[-1] exactly (fp32)
        }
        float Wre, Wim;
        dft441_fwd_reg(sx, sb1, sb2, tid, act, &Wre, &Wim);
        if (act) {
            ((float2*)g_what)[tid] = make_float2(Wre, Wim);
            float rr  = decay * cosf((PI_F * (float)tid) / 441.0f);
            float mag = powf(fabsf(rr), (float)BB);   // BB even -> sign drops
            int   k2  = (BB * tid) % (2 * WSZ);
            float angp = -(PI_F * (float)k2) / 441.0f;
            float sp, cp; sincosf(angp, &sp, &cp);
            ((float2*)g_lamB)[tid] = make_float2(mag * cp, mag * sp);
        }
    }

    // ---- pass A: forced response from zero; overwrite consumed fb rows ----
    int i = tid;
    int iw[KH + 1];
    if (act) {
        #pragma unroll
        for (int m = 0; m <= KH; m++) { int v = i - m; if (v < 0) v += WSZ; iw[m] = v; }
    } else {
        #pragma unroll
        for (int m = 0; m <= KH; m++) iw[m] = 0;
    }

    float* ob = aux;                   // 2*WSZ double buffer (reuses sx/sy)
    if (act) ob[tid] = 0.0f;
    int cb = 0;
    __syncthreads();

    for (int grp = 0; grp < NG; grp++) {
        int b = grp * KH;
        float O[KH + 1], X[KH + 1], Fout[KH];
        if (act) {
            const float* obr = ob + cb * WSZ;
            #pragma unroll
            for (int m = 0; m <= KH; m++) O[m] = obr[iw[KH - m]];
            #pragma unroll
            for (int j = 0; j < KH; j++) {
                const float* fr = sfb + (b + j) * WSZ;
                #pragma unroll
                for (int m = j; m <= KH; m++) X[m] = fmaf(fa, fr[iw[KH - m]], O[m]);
                #pragma unroll
                for (int m = KH; m > j; m--) O[m] = c * (X[m] + X[m - 1]);
                Fout[j] = O[KH];
            }
            ob[(cb ^ 1) * WSZ + i] = O[KH];
        }
        __syncthreads();
        if (act) {
            #pragma unroll
            for (int j = 0; j < KH; j++) sfb[(b + j) * WSZ + i] = Fout[j];
        }
        cb ^= 1;
    }

    // ---- forward DFT of forced end state -> g_Ehat[g] ----
    {
        float Ere = 0.0f, Eim = 0.0f;
        dft441_fwd_reg(ob + cb * WSZ, aux + 2 * WSZ, aux + 3 * WSZ, tid, act, &Ere, &Eim);
        if (act)
            ((float2*)(g_Ehat + (size_t)g * 2 * WSZ))[tid] = make_float2(Ere, Eim);
    }

    // ---- bulk-store forced rows to out (scratch), vectorized ----
    {
        const float4* s4 = (const float4*)sfb;
        float4* o4 = (float4*)(out + (size_t)g * BB * WSZ);
        #pragma unroll
        for (int k = 0; k < 9; k++) o4[tid + NTHR * k] = s4[tid + NTHR * k];
        if (tid < NV4 - 9 * NTHR) o4[tid + 9 * NTHR] = s4[tid + 9 * NTHR];
    }
}

// ---------------- K_scan: sequential scan over blocks (per bin) -----------
__global__ __launch_bounds__(WSZ)
void k_scan() {
    int m = threadIdx.x;
    float2 W = ((const float2*)g_what)[m];
    float2 L = ((const float2*)g_lamB)[m];
    float sre = W.x, sim = W.y;
    float2* Sh = (float2*)g_Shat;
    const float2* Eh = (const float2*)g_Ehat;
    #pragma unroll 5
    for (int g = 0; g < GG; g++) {
        Sh[g * WSZ + m] = make_float2(sre, sim);
        float2 E = Eh[g * WSZ + m];
        float nre = fmaf(L.x, sre, fmaf(-L.y, sim, E.x));
        float nim = fmaf(L.x, sim, fmaf( L.y, sre, E.y));
        sre = nre; sim = nim;
    }
}

// ---------------- K_B: iDFT + homogeneous recurrence + epilogue -----------
__global__ __launch_bounds__(NTHR, 2)
void k_passB(const float* __restrict__ fade, float* __restrict__ out) {
    extern __shared__ float smx[];
    float* sfb = smx;                  // BB*WSZ (forced rows, from out scratch)
    float* aux = smx + BB * WSZ;       // 6*WSZ

    int tid = threadIdx.x;
    int g   = blockIdx.x;
    bool act = tid < WSZ;

    // stage forced rows (float4)
    {
        const float4* f4 = (const float4*)(out + (size_t)g * BB * WSZ);
        float4* s4 = (float4*)sfb;
        #pragma unroll
        for (int k = 0; k < 9; k++) s4[tid + NTHR * k] = f4[tid + NTHR * k];
        if (tid < NV4 - 9 * NTHR) s4[tid + 9 * NTHR] = f4[tid + 9 * NTHR];
    }

    float* ob  = aux;                  // 2*WSZ
    float* sre = aux + 2 * WSZ;
    float* sim = aux + 3 * WSZ;
    float* Hre = aux + 4 * WSZ;
    float* Him = aux + 5 * WSZ;

    if (act) {
        float2 v = ((const float2*)(g_Shat + (size_t)g * 2 * WSZ))[tid];
        sre[tid] = v.x; sim[tid] = v.y;
    }
    float c    = g_scal[0];
    float sA   = g_scal[2];
    float inva = g_scal[3];
    float invr = g_scal[5];
    float T    = g_scal[6];
    __syncthreads();

    // inverse DFT (radix-21): x[i] = (1/441) Re{ sum_m S[m] e^{+2pi i m i/441} }
    int i = tid;
    if (act) {   // stage 1: tid = m0*21 + imod
        int m0 = tid / R21, imod = tid % R21;
        float ang = TWOPI_F * (float)imod / 21.0f;
        float c0, s0; sincosf(ang, &s0, &c0);
        float wc = 1.0f, ws = 0.0f, hre = 0.0f, him = 0.0f;
        #pragma unroll
        for (int m1 = 0; m1 < R21; m1++) {
            float a = sre[m0 + R21 * m1];
            float b = sim[m0 + R21 * m1];
            hre = fmaf(a, wc, fmaf(-b, ws, hre));
            him = fmaf(a, ws, fmaf( b, wc, him));
            float nw = wc * c0 - ws * s0;
            ws = fmaf(wc, s0, ws * c0);
            wc = nw;
        }
        Hre[tid] = hre; Him[tid] = him;
    }
    __syncthreads();
    if (act) {   // stage 2: tid = i (real part only)
        int im21 = i % R21;
        float ang = TWOPI_F * (float)i / 441.0f;
        float c0, s0; sincosf(ang, &s0, &c0);
        float wc = 1.0f, ws = 0.0f, acc = 0.0f;
        #pragma unroll
        for (int m0 = 0; m0 < R21; m0++) {
            float a = Hre[m0 * R21 + im21];
            float b = Him[m0 * R21 + im21];
            acc = fmaf(a, wc, fmaf(-b, ws, acc));
            float nw = wc * c0 - ws * s0;
            ws = fmaf(wc, s0, ws * c0);
            wc = nw;
        }
        ob[i] = acc * (1.0f / 441.0f);
    }
    __syncthreads();

    int iw[KH + 1];
    if (act) {
        #pragma unroll
        for (int m = 0; m <= KH; m++) { int v = i - m; if (v < 0) v += WSZ; iw[m] = v; }
    } else {
        #pragma unroll
        for (int m = 0; m <= KH; m++) iw[m] = 0;
    }

    // homogeneous recurrence; out = homog + forced(row)
    int nbase = g * BB * WSZ + i;
    int cb = 0;
    for (int grp = 0; grp < NG; grp++) {
        int b = grp * KH;
        float O[KH + 1];
        if (act) {
            const float* obr = ob + cb * WSZ;
            #pragma unroll
            for (int m = 0; m <= KH; m++) O[m] = obr[iw[KH - m]];
            #pragma unroll
            for (int j = 0; j < KH; j++) {
                #pragma unroll
                for (int m = KH; m > j; m--) O[m] = c * (O[m] + O[m - 1]);

                float v = O[KH] + sfb[(b + j) * WSZ + i];
                int n = nbase + (b + j) * WSZ;
                if (n >= N_SAMPLES - 256) v *= fade[n - (N_SAMPLES - 256)];
                float tn = (float)n * (1.0f / SR_F);
                float e1 = __saturatef(tn * inva);
                float e2 = __saturatef((T - tn) * invr);
                out[n] = v * (e1 * e2) * sA;
            }
            ob[(cb ^ 1) * WSZ + i] = O[KH];
        }
        __syncthreads();
        cb ^= 1;
    }
}

// ---------------- host entry --------------------------------------------
extern "C" void kernel_launch(void* const* d_in, const int* in_sizes, int n_in,
                              void* d_out, int out_size) {
    const float* fb    = (const float*)d_in[0];   // feedback_line [4410000]
    const float* h     = (const float*)d_in[1];   // h [1,9]
    // d_in[2] = t — unused (t[n] == n/44100 exactly in fp32)
    const float* noise = (const float*)d_in[3];   // wavetable_noise [441]
    const float* W1    = (const float*)d_in[4];   // [9,128]
    const float* b1    = (const float*)d_in[5];   // [128]
    const float* W2    = (const float*)d_in[6];   // [128,5]
    const float* b2    = (const float*)d_in[7];   // [5]
    const float* lp    = (const float*)d_in[8];   // lp_cutoff [1]
    const float* env   = (const float*)d_in[9];   // env_params [3]
    const float* fade  = (const float*)d_in[10];  // fade [256]
    float* out = (float*)d_out;

    const int ds = (BB * WSZ + 6 * WSZ) * (int)sizeof(float);  // 81,144 B
    cudaFuncSetAttribute(k_passA, cudaFuncAttributeMaxDynamicSharedMemorySize, ds);
    cudaFuncSetAttribute(k_passB, cudaFuncAttributeMaxDynamicSharedMemorySize, ds);

    k_passA<<<GG, NTHR, ds>>>(fb, h, noise, W1, b1, W2, b2, lp, env, out);
    k_scan<<<1, WSZ>>>();
    k_passB<<<GG, NTHR, ds>>>(fade, out);
}

// round 8
// speedup vs baseline: 2.1927x; 2.1927x over previous
#include <cuda_runtime.h>
#include <math.h>

// ---------------- problem constants (static in reference) ----------------
#define N_SAMPLES 4410000
#define WSZ       441          // wavetable size
#define BB        80           // chunks per block
#define GG        125          // number of blocks (BB*GG == 10000 chunks)
#define KH        4            // recurrence steps per barrier (halo depth)
#define NG        (BB / KH)    // 20 barrier groups
#define R21       21           // radix (441 = 21*21)

#define PI_F      3.14159265358979f
#define TWOPI_F   6.2831853071795864f
#define SR_F      44100.0f

// ---------------- device scratch ----------------------------------------
__device__ float g_what[2 * WSZ];      // DFT of wavetable
__device__ float g_lamB[2 * WSZ];      // lambda^BB per bin
__device__ float g_Ehat[GG * 2 * WSZ]; // per-block forced end-state spectra
__device__ float g_scal[8];            // 0:c 1:fa 2:sA 3:inv_a 5:inv_r 6:T

// ---------------- parallel biquad via affine scan ------------------------
__device__ void biquad_par(const float* __restrict__ x, float* __restrict__ y,
                           float f, float q, int tid,
                           float* sb1, float* sb2, float (*sMp)[4]) {
    float w0   = (TWOPI_F * f) / SR_F;
    float cosw = cosf(w0);
    float alpha = sinf(w0) / (2.0f * q);
    float b0 = (1.0f - cosw) / 2.0f;
    float b1c = 1.0f - cosw;
    float b2c = (1.0f - cosw) / 2.0f;
    float a0 = 1.0f + alpha;
    float a1 = -2.0f * cosw;
    float a2 = 1.0f - alpha;
    b0 /= a0; b1c /= a0; b2c /= a0; a1 /= a0; a2 /= a0;
    float d1 = b1c - a1 * b0;
    float d2 = b2c - a2 * b0;

    if (tid == 0) {
        float A0 = -a1, A1 = 1.0f, A2 = -a2, A3 = 0.0f;
        #pragma unroll
        for (int dd = 0; dd < 9; dd++) {
            sMp[dd][0] = A0; sMp[dd][1] = A1; sMp[dd][2] = A2; sMp[dd][3] = A3;
            float n0 = A0 * A0 + A1 * A2;
            float n1 = A0 * A1 + A1 * A3;
            float n2 = A2 * A0 + A3 * A2;
            float n3 = A2 * A1 + A3 * A3;
            A0 = n0; A1 = n1; A2 = n2; A3 = n3;
        }
    }
    float xv = x[tid];
    sb1[tid] = xv * d1;
    sb2[tid] = xv * d2;
    __syncthreads();
    #pragma unroll
    for (int dd = 0; dd < 9; dd++) {
        int off = 1 << dd;
        float p1 = 0.0f, p2 = 0.0f;
        if (tid >= off) { p1 = sb1[tid - off]; p2 = sb2[tid - off]; }
        float m0 = sMp[dd][0], m1 = sMp[dd][1], m2 = sMp[dd][2], m3 = sMp[dd][3];
        __syncthreads();
        if (tid >= off) {
            sb1[tid] = fmaf(m0, p1, fmaf(m1, p2, sb1[tid]));
            sb2[tid] = fmaf(m2, p1, fmaf(m3, p2, sb2[tid]));
        }
        __syncthreads();
    }
    float s1 = (tid == 0) ? 0.0f : sb1[tid - 1];
    y[tid] = fmaf(b0, xv, s1);
    __syncthreads();
}

// ---------------- radix-21 forward DFT (smem -> per-thread register bin) --
__device__ __forceinline__ void dft441_fwd_reg(const float* __restrict__ sx,
                                               float* __restrict__ t_re,
                                               float* __restrict__ t_im,
                                               int tid, float* oRe, float* oIm) {
    {   // stage 1: tid = mmod*21 + i0
        int mmod = tid / R21, i0 = tid % R21;
        float ang = -TWOPI_F * (float)mmod / 21.0f;
        float c0, s0; sincosf(ang, &s0, &c0);
        float wc = 1.0f, ws = 0.0f, re = 0.0f, im = 0.0f;
        #pragma unroll
        for (int i1 = 0; i1 < R21; i1++) {
            float v = sx[i0 + R21 * i1];
            re = fmaf(v, wc, re);
            im = fmaf(v, ws, im);
            float nw = wc * c0 - ws * s0;
            ws = fmaf(wc, s0, ws * c0);
            wc = nw;
        }
        t_re[tid] = re; t_im[tid] = im;
    }
    __syncthreads();
    {   // stage 2: tid = m
        int m = tid, mm = m % R21;
        float ang = -TWOPI_F * (float)m / 441.0f;
        float c0, s0; sincosf(ang, &s0, &c0);
        float wc = 1.0f, ws = 0.0f, re = 0.0f, im = 0.0f;
        const float* gr = t_re + mm * R21;
        const float* gi = t_im + mm * R21;
        #pragma unroll
        for (int i0 = 0; i0 < R21; i0++) {
            float a = gr[i0], b = gi[i0];
            re = fmaf(a, wc, fmaf(-b, ws, re));
            im = fmaf(a, ws, fmaf( b, wc, im));
            float nw = wc * c0 - ws * s0;
            ws = fmaf(wc, s0, ws * c0);
            wc = nw;
        }
        *oRe = re; *oIm = im;
    }
    __syncthreads();   // callers reuse the temps after this
}

// ---------------- K_A: setup (redundant per CTA) + pass A -----------------
__global__ __launch_bounds__(WSZ, 1)
void k_passA(const float* __restrict__ fb,   const float* __restrict__ h,
             const float* __restrict__ noise, const float* __restrict__ W1,
             const float* __restrict__ b1,   const float* __restrict__ W2,
             const float* __restrict__ b2,   const float* __restrict__ lp,
             const float* __restrict__ env,  float* __restrict__ out) {
    extern __shared__ float smx[];
    float* sfb = smx;                  // BB*WSZ (fb tile; overwritten with forced rows)
    float* aux = smx + BB * WSZ;       // 6*WSZ scratch

    int tid = threadIdx.x;
    int g   = blockIdx.x;

    // stage fb tile as float4 (BB*WSZ = 8820 float4)
    {
        const float4* f4 = (const float4*)(fb + (size_t)g * BB * WSZ);
        float4* s4 = (float4*)sfb;
        #pragma unroll
        for (int k = 0; k < 20; k++) s4[tid + WSZ * k] = f4[tid + WSZ * k];
    }

    // redundant per-CTA setup
    float* sx   = aux;
    float* sy   = aux + WSZ;
    float* sb1  = aux + 2 * WSZ;
    float* sb2  = aux + 3 * WSZ;
    float* shid = aux + 4 * WSZ;          // 128
    float* slat = aux + 4 * WSZ + 128;    // 5
    float (*sMp)[4] = (float(*)[4])(aux + 4 * WSZ + 160); // 36

    if (tid < 128) {
        float acc = b1[tid];
        #pragma unroll
        for (int i = 0; i < 9; i++) acc += h[i] * W1[i * 128 + tid];
        shid[tid] = fmaxf(acc, 0.0f);
    }
    sx[tid] = noise[tid];
    __syncthreads();
    if (tid < 5) {
        float acc = b2[tid];
        for (int j = 0; j < 128; j++) acc += shid[j] * W2[j * 5 + tid];
        slat[tid] = fmaxf(acc, 0.0f);
    }
    __syncthreads();

    float l0 = slat[0], l1 = slat[1], l2 = slat[2], l3 = slat[3], l4 = slat[4];
    float decay = fminf(fmaxf(l0 / 10.0f + 0.9f, 0.9f), 0.999f);
    float lpf = fminf(fmaxf(l1 * SR_F / 4.0f, 100.0f), SR_F / 2.0f - 1.0f);
    float lpq = fminf(fmaxf(l2, 0.1f), 0.999f);

    biquad_par(sx, sy, lpf, lpq, tid, sb1, sb2, sMp);
    biquad_par(sy, sx, lp[0], 0.707f, tid, sb1, sb2, sMp);
    // sx = wavetable wt

    float c  = decay * 0.5f;
    float fa = l3;

    if (g == 0 && tid == 0) {
        g_scal[0] = c;
        g_scal[1] = fa;
        g_scal[2] = env[1] * l4;                    // s * gain
        g_scal[3] = 1.0f / (fabsf(env[0]) + 1e-3f); // 1/attack
        g_scal[5] = 1.0f / (fabsf(env[2]) + 1e-3f); // 1/release
        g_scal[6] = (float)(N_SAMPLES - 1) / SR_F;  // T == t[-1] exactly (fp32)
    }

    // wavetable DFT + lambda^BB -> global (CTA 0 publishes; all CTAs compute)
    {
        float Wre, Wim;
        dft441_fwd_reg(sx, sb1, sb2, tid, &Wre, &Wim);
        if (g == 0) {
            ((float2*)g_what)[tid] = make_float2(Wre, Wim);
            float rr  = decay * cosf((PI_F * (float)tid) / 441.0f);
            float mag = powf(fabsf(rr), (float)BB);   // BB even -> sign drops
            int   k2  = (BB * tid) % (2 * WSZ);
            float angp = -(PI_F * (float)k2) / 441.0f;
            float sp, cp; sincosf(angp, &sp, &cp);
            ((float2*)g_lamB)[tid] = make_float2(mag * cp, mag * sp);
        }
    }

    int i = tid;
    int iw[KH + 1];
    #pragma unroll
    for (int m = 0; m <= KH; m++) { int v = i - m; if (v < 0) v += WSZ; iw[m] = v; }

    // pass A: forced response from zero; overwrite consumed fb rows in smem
    float* ob = aux;                   // 2*WSZ double buffer
    ob[tid] = 0.0f;
    int cb = 0;
    __syncthreads();

    for (int grp = 0; grp < NG; grp++) {
        int b = grp * KH;
        float O[KH + 1], X[KH + 1], Fout[KH];
        const float* obr = ob + cb * WSZ;
        #pragma unroll
        for (int m = 0; m <= KH; m++) O[m] = obr[iw[KH - m]];
        #pragma unroll
        for (int j = 0; j < KH; j++) {
            const float* fr = sfb + (b + j) * WSZ;
            #pragma unroll
            for (int m = j; m <= KH; m++) X[m] = fmaf(fa, fr[iw[KH - m]], O[m]);
            #pragma unroll
            for (int m = KH; m > j; m--) O[m] = c * (X[m] + X[m - 1]);
            Fout[j] = O[KH];
        }
        ob[(cb ^ 1) * WSZ + i] = O[KH];
        __syncthreads();
        // rows b..b+KH-1 fully consumed by all threads -> safe to overwrite
        #pragma unroll
        for (int j = 0; j < KH; j++) sfb[(b + j) * WSZ + i] = Fout[j];
        cb ^= 1;
    }

    // forward DFT of forced end state -> g_Ehat[g]
    {
        float Ere, Eim;
        dft441_fwd_reg(ob + cb * WSZ, aux + 2 * WSZ, aux + 3 * WSZ, tid, &Ere, &Eim);
        ((float2*)(g_Ehat + (size_t)g * 2 * WSZ))[tid] = make_float2(Ere, Eim);
    }

    // bulk-store forced rows to out (scratch), vectorized
    {
        const float4* s4 = (const float4*)sfb;
        float4* o4 = (float4*)(out + (size_t)g * BB * WSZ);
        #pragma unroll
        for (int k = 0; k < 20; k++) o4[tid + WSZ * k] = s4[tid + WSZ * k];
    }
}

// ---------------- K_B: per-CTA scan + iDFT + homog recurrence + epilogue --
__global__ __launch_bounds__(WSZ, 1)
void k_passB(const float* __restrict__ fade, float* __restrict__ out) {
    extern __shared__ float smx[];
    float* sfb = smx;                  // BB*WSZ (forced rows, from out scratch)
    float* aux = smx + BB * WSZ;       // 6*WSZ

    int tid = threadIdx.x;
    int g   = blockIdx.x;

    // stage forced rows (float4)
    {
        const float4* f4 = (const float4*)(out + (size_t)g * BB * WSZ);
        float4* s4 = (float4*)sfb;
        #pragma unroll
        for (int k = 0; k < 20; k++) s4[tid + WSZ * k] = f4[tid + WSZ * k];
    }

    float* ob  = aux;                  // 2*WSZ
    float* sre = aux + 2 * WSZ;
    float* sim = aux + 3 * WSZ;
    float* Hre = aux + 4 * WSZ;
    float* Him = aux + 5 * WSZ;

    float c    = g_scal[0];
    float sA   = g_scal[2];
    float inva = g_scal[3];
    float invr = g_scal[5];
    float T    = g_scal[6];

    // per-CTA spectral scan: S_g = sum of lam^B-propagated block responses.
    // S = What; for g' in [0, g): S = L*S + Ehat[g'].  (kernel boundary made
    // all Ehat visible; CTA 0 does zero iterations.)
    {
        float2 W = ((const float2*)g_what)[tid];
        float2 L = ((const float2*)g_lamB)[tid];
        float Sre = W.x, Sim = W.y;
        const float2* Eh = (const float2*)g_Ehat;
        int gp = 0;
        #pragma unroll 4
        for (; gp < g; gp++) {
            float2 E = Eh[gp * WSZ + tid];
            float nre = fmaf(L.x, Sre, fmaf(-L.y, Sim, E.x));
            float nim = fmaf(L.x, Sim, fmaf( L.y, Sre, E.y));
            Sre = nre; Sim = nim;
        }
        sre[tid] = Sre; sim[tid] = Sim;
    }
    __syncthreads();

    // inverse DFT (radix-21): x[i] = (1/441) Re{ sum_m S[m] e^{+2pi i m i/441} }
    int i = tid;
    {   // stage 1: tid = m0*21 + imod
        int m0 = tid / R21, imod = tid % R21;
        float ang = TWOPI_F * (float)imod / 21.0f;
        float c0, s0; sincosf(ang, &s0, &c0);
        float wc = 1.0f, ws = 0.0f, hre = 0.0f, him = 0.0f;
        #pragma unroll
        for (int m1 = 0; m1 < R21; m1++) {
            float a = sre[m0 + R21 * m1];
            float b = sim[m0 + R21 * m1];
            hre = fmaf(a, wc, fmaf(-b, ws, hre));
            him = fmaf(a, ws, fmaf( b, wc, him));
            float nw = wc * c0 - ws * s0;
            ws = fmaf(wc, s0, ws * c0);
            wc = nw;
        }
        Hre[tid] = hre; Him[tid] = him;
    }
    __syncthreads();
    {   // stage 2: tid = i (real part only)
        int im21 = i % R21;
        float ang = TWOPI_F * (float)i / 441.0f;
        float c0, s0; sincosf(ang, &s0, &c0);
        float wc = 1.0f, ws = 0.0f, acc = 0.0f;
        #pragma unroll
        for (int m0 = 0; m0 < R21; m0++) {
            float a = Hre[m0 * R21 + im21];
            float b = Him[m0 * R21 + im21];
            acc = fmaf(a, wc, fmaf(-b, ws, acc));
            float nw = wc * c0 - ws * s0;
            ws = fmaf(wc, s0, ws * c0);
            wc = nw;
        }
        ob[i] = acc * (1.0f / 441.0f);
    }
    __syncthreads();

    int iw[KH + 1];
    #pragma unroll
    for (int m = 0; m <= KH; m++) { int v = i - m; if (v < 0) v += WSZ; iw[m] = v; }

    // homogeneous recurrence; out = homog + forced(row)
    int nbase = g * BB * WSZ + i;
    int cb = 0;
    for (int grp = 0; grp < NG; grp++) {
        int b = grp * KH;
        float O[KH + 1];
        const float* obr = ob + cb * WSZ;
        #pragma unroll
        for (int m = 0; m <= KH; m++) O[m] = obr[iw[KH - m]];
        #pragma unroll
        for (int j = 0; j < KH; j++) {
            #pragma unroll
            for (int m = KH; m > j; m--) O[m] = c * (O[m] + O[m - 1]);

            float v = O[KH] + sfb[(b + j) * WSZ + i];
            int n = nbase + (b + j) * WSZ;
            if (n >= N_SAMPLES - 256) v *= fade[n - (N_SAMPLES - 256)];
            float tn = (float)n * (1.0f / SR_F);
            float e1 = __saturatef(tn * inva);
            float e2 = __saturatef((T - tn) * invr);
            out[n] = v * (e1 * e2) * sA;
        }
        ob[(cb ^ 1) * WSZ + i] = O[KH];
        __syncthreads();
        cb ^= 1;
    }
}

// ---------------- host entry --------------------------------------------
extern "C" void kernel_launch(void* const* d_in, const int* in_sizes, int n_in,
                              void* d_out, int out_size) {
    const float* fb    = (const float*)d_in[0];   // feedback_line [4410000]
    const float* h     = (const float*)d_in[1];   // h [1,9]
    // d_in[2] = t — unused (t[n] == n/44100 exactly in fp32)
    const float* noise = (const float*)d_in[3];   // wavetable_noise [441]
    const float* W1    = (const float*)d_in[4];   // [9,128]
    const float* b1    = (const float*)d_in[5];   // [128]
    const float* W2    = (const float*)d_in[6];   // [128,5]
    const float* b2    = (const float*)d_in[7];   // [5]
    const float* lp    = (const float*)d_in[8];   // lp_cutoff [1]
    const float* env   = (const float*)d_in[9];   // env_params [3]
    const float* fade  = (const float*)d_in[10];  // fade [256]
    float* out = (float*)d_out;

    const int ds = (BB * WSZ + 6 * WSZ) * (int)sizeof(float);  // 151,704 B
    cudaFuncSetAttribute(k_passA, cudaFuncAttributeMaxDynamicSharedMemorySize, ds);
    cudaFuncSetAttribute(k_passB, cudaFuncAttributeMaxDynamicSharedMemorySize, ds);

    k_passA<<<GG, WSZ, ds>>>(fb, h, noise, W1, b1, W2, b2, lp, env, out);
    k_passB<<<GG, WSZ, ds>>>(fade, out);
}